// round 1
// baseline (speedup 1.0000x reference)
#include <cuda_runtime.h>
#include <cuda_bf16.h>
#include <math.h>

// ---------------- problem constants ----------------
#define BB 2
#define NN 2048
#define DD 128
#define HH 8
#define DH 16
#define LL 3
#define ROWS (BB*NN)        // 4096
#define SCALE 0.25f         // 1/sqrt(16)
#define NEG   (-1e9f)
#define EPS   1e-5f

// ---------------- scratch (device globals; no allocation allowed) ----------
__device__ float g_h  [ROWS*DD];       // residual stream
__device__ float g_x  [ROWS*DD];       // LN output
__device__ float g_qkv[ROWS*3*DD];     // qkv
__device__ float g_o  [ROWS*DD];       // attention out
__device__ float g_f  [ROWS*4*DD];     // ff hidden
__device__ int   g_isatom[ROWS];
__device__ int   g_mask  [ROWS];

// ---------------- bool normalization (format-agnostic) ----------------
// Detects whether the buffer holds 1-byte bools or 4-byte values (int32 0/1
// or float32 0/1.0) and writes canonical int 0/1.
__global__ void norm_bool_kernel(const unsigned char* __restrict__ raw, int count,
                                 int* __restrict__ out) {
    __shared__ int s_other;
    if (threadIdx.x == 0) s_other = 0;
    __syncthreads();
    const unsigned int* w = (const unsigned int*)raw;
    int nw = count / 4;
    int other = 0;
    for (int i = threadIdx.x; i < nw; i += blockDim.x) {
        unsigned int v = w[i];
        if (v != 0u && v != 1u && v != 0x3f800000u) other = 1;
    }
    if (other) atomicOr(&s_other, 1);
    __syncthreads();
    bool byteFmt = (s_other != 0);
    for (int i = threadIdx.x; i < count; i += blockDim.x) {
        out[i] = byteFmt ? (raw[i] != 0) : (w[i] != 0u);
    }
}

// ---------------- embedding gather ----------------
__global__ void embed_kernel(const float* __restrict__ atom_embed,
                             const float* __restrict__ cons_embed,
                             const int* __restrict__ atom_id,
                             const int* __restrict__ isatom,
                             float* __restrict__ e) {
    int row = blockIdx.x, t = threadIdx.x;
    int id = atom_id[row];
    id = id < 0 ? 0 : (id > 31 ? 31 : id);
    float v = isatom[row] ? atom_embed[id*DD + t] : cons_embed[t];
    e[row*DD + t] = v;
}

// ---------------- block reduction helper (128 threads) ----------------
__device__ __forceinline__ float blockReduceSum128(float v, float* sred) {
    #pragma unroll
    for (int o = 16; o; o >>= 1) v += __shfl_xor_sync(0xffffffffu, v, o);
    int wid = threadIdx.x >> 5;
    if ((threadIdx.x & 31) == 0) sred[wid] = v;
    __syncthreads();
    float r = sred[0] + sred[1] + sred[2] + sred[3];
    __syncthreads();
    return r;
}

// ---------------- LayerNorm (one row of 128 per block) ----------------
__global__ void ln_kernel(const float* __restrict__ in, const float* __restrict__ g,
                          const float* __restrict__ b, float* __restrict__ out) {
    __shared__ float sred[4];
    int row = blockIdx.x, t = threadIdx.x;
    float v = in[row*DD + t];
    float mean = blockReduceSum128(v, sred) * (1.0f/DD);
    float d = v - mean;
    float var = blockReduceSum128(d*d, sred) * (1.0f/DD);
    out[row*DD + t] = d * rsqrtf(var + EPS) * g[t] + b[t];
}

// ---------------- GEMM: C[M,Nc] = A[M,K] @ W[Nc,K]^T + bias (+epilogue) -----
// MODE 0: +bias  | MODE 1: +bias +res (may alias C) | MODE 2: +bias then GELU
template<int MODE>
__global__ void gemm_kernel(const float* __restrict__ A, const float* __restrict__ W,
                            const float* __restrict__ bias, const float* __restrict__ res,
                            float* __restrict__ C, int M, int Nc, int K) {
    __shared__ float As[64*33];
    __shared__ float Ws[64*33];
    int tx = threadIdx.x & 15, ty = threadIdx.x >> 4;
    int m0 = blockIdx.y * 64, n0 = blockIdx.x * 64;
    float acc[4][4] = {};
    for (int k0 = 0; k0 < K; k0 += 32) {
        #pragma unroll
        for (int r = 0; r < 2; r++) {
            int idx = threadIdx.x + r*256;       // 0..511 float4 slots
            int row = idx >> 3, c4 = idx & 7;
            float4 va = *(const float4*)(A + (size_t)(m0+row)*K + k0 + c4*4);
            float* da = As + row*33 + c4*4;
            da[0]=va.x; da[1]=va.y; da[2]=va.z; da[3]=va.w;
            float4 vb = *(const float4*)(W + (size_t)(n0+row)*K + k0 + c4*4);
            float* db = Ws + row*33 + c4*4;
            db[0]=vb.x; db[1]=vb.y; db[2]=vb.z; db[3]=vb.w;
        }
        __syncthreads();
        #pragma unroll
        for (int kk = 0; kk < 32; kk++) {
            float a[4], w[4];
            #pragma unroll
            for (int i = 0; i < 4; i++) a[i] = As[(ty*4+i)*33 + kk];
            #pragma unroll
            for (int j = 0; j < 4; j++) w[j] = Ws[(tx*4+j)*33 + kk];
            #pragma unroll
            for (int i = 0; i < 4; i++)
                #pragma unroll
                for (int j = 0; j < 4; j++)
                    acc[i][j] += a[i] * w[j];
        }
        __syncthreads();
    }
    #pragma unroll
    for (int i = 0; i < 4; i++) {
        int r = m0 + ty*4 + i;
        #pragma unroll
        for (int j = 0; j < 4; j++) {
            int c = n0 + tx*4 + j;
            float v = acc[i][j] + bias[c];
            if (MODE == 1) v += res[(size_t)r*Nc + c];
            if (MODE == 2) v = 0.5f * v * (1.0f + erff(v * 0.70710678118654752f));
            C[(size_t)r*Nc + c] = v;
        }
    }
}

// ---------------- flash attention: all heads per query block ----------------
// Grid: (N/32, B), 256 threads. Thread (h=tid>>5, qi=tid&31) owns one
// (head, query-row) with a 16-wide register accumulator + online softmax.
__global__ void attn_kernel(const float* __restrict__ qkv, const float* __restrict__ adj,
                            const int* __restrict__ mask, const float* __restrict__ sbp,
                            float* __restrict__ o) {
    extern __shared__ float sm[];
    float* sK   = sm;                    // 64*128
    float* sV   = sK + 64*128;           // 64*128
    float* sAdj = sV + 64*128;           // 64*33  (kj-major, padded)
    int*   sMk  = (int*)(sAdj + 64*33);  // 64

    int b = blockIdx.y, n0 = blockIdx.x * 32;
    int tid = threadIdx.x;
    int qi = tid & 31, hh = tid >> 5;
    float sb = *sbp;

    int qrow = b*NN + n0 + qi;
    float4 q4[4];
    const float4* qp = (const float4*)(qkv + (size_t)qrow*384 + hh*DH);
    #pragma unroll
    for (int i = 0; i < 4; i++) q4[i] = qp[i];
    int mq = mask[qrow];

    float m = -INFINITY, l = 0.0f;
    float acc[16];
    #pragma unroll
    for (int d = 0; d < 16; d++) acc[d] = 0.0f;

    const float* adjb = adj + (size_t)b*NN*NN;

    for (int k0 = 0; k0 < NN; k0 += 64) {
        #pragma unroll
        for (int r = 0; r < 8; r++) {
            int idx = tid + r*256;           // 0..2047 float4 slots
            int row = idx >> 5, c4 = idx & 31;
            const float* base = qkv + (size_t)(b*NN + k0 + row)*384;
            *(float4*)(sK + row*128 + c4*4) = *(const float4*)(base + 128 + c4*4);
            *(float4*)(sV + row*128 + c4*4) = *(const float4*)(base + 256 + c4*4);
        }
        #pragma unroll
        for (int r = 0; r < 8; r++) {
            int idx = tid + r*256;           // 0..2047
            int q2 = idx >> 6, kj = idx & 63;
            sAdj[kj*33 + q2] = adjb[(size_t)(n0 + q2)*NN + k0 + kj];
        }
        if (tid < 64) sMk[tid] = mask[b*NN + k0 + tid];
        __syncthreads();

        #pragma unroll 4
        for (int kj = 0; kj < 64; kj++) {
            const float4* kp = (const float4*)(sK + kj*128 + hh*DH);
            float s = 0.0f;
            #pragma unroll
            for (int i = 0; i < 4; i++) {
                float4 kv = kp[i];
                s += q4[i].x*kv.x + q4[i].y*kv.y + q4[i].z*kv.z + q4[i].w*kv.w;
            }
            int mk = sMk[kj];
            bool ok = (mq && mk) || (!mq && (n0 + qi == k0 + kj));
            s = s*SCALE + sb*sAdj[kj*33 + qi] + (ok ? 0.0f : NEG);

            if (s > m) {
                float corr = __expf(m - s);
                m = s; l *= corr;
                #pragma unroll
                for (int d = 0; d < 16; d++) acc[d] *= corr;
            }
            float p = __expf(s - m);
            l += p;
            const float4* vp = (const float4*)(sV + kj*128 + hh*DH);
            #pragma unroll
            for (int i = 0; i < 4; i++) {
                float4 vv = vp[i];
                acc[i*4+0] += p*vv.x; acc[i*4+1] += p*vv.y;
                acc[i*4+2] += p*vv.z; acc[i*4+3] += p*vv.w;
            }
        }
        __syncthreads();
    }
    float inv = 1.0f / l;
    float* op = o + (size_t)qrow*DD + hh*DH;
    #pragma unroll
    for (int d = 0; d < 16; d++) op[d] = acc[d] * inv;
}

// ---------------- head: gather root, LN, dot ----------------
__global__ void head_kernel(const float* __restrict__ h, const float* __restrict__ g,
                            const float* __restrict__ bb, const float* __restrict__ w,
                            const float* __restrict__ hb, const int* __restrict__ root,
                            float* __restrict__ out) {
    __shared__ float sred[4];
    int t = threadIdx.x;
    for (int b = 0; b < BB; b++) {
        int row = root[b];
        float v = h[((size_t)b*NN + row)*DD + t];
        float mean = blockReduceSum128(v, sred) * (1.0f/DD);
        float d = v - mean;
        float var = blockReduceSum128(d*d, sred) * (1.0f/DD);
        float p = d * rsqrtf(var + EPS) * g[t] + bb[t];
        float s = blockReduceSum128(p * w[t], sred);
        if (t == 0) out[b] = s + hb[0];
    }
}

// ---------------- launch ----------------
extern "C" void kernel_launch(void* const* d_in, const int* in_sizes, int n_in,
                              void* d_out, int out_size) {
    const float* atom_embed = (const float*)d_in[0];
    const float* cons_embed = (const float*)d_in[1];
    const float* in_w   = (const float*)d_in[2];
    const float* in_b   = (const float*)d_in[3];
    const float* qkv_w  = (const float*)d_in[4];
    const float* qkv_b  = (const float*)d_in[5];
    const float* out_w  = (const float*)d_in[6];
    const float* out_b  = (const float*)d_in[7];
    const float* ln1_g  = (const float*)d_in[8];
    const float* ln1_b  = (const float*)d_in[9];
    const float* ln2_g  = (const float*)d_in[10];
    const float* ln2_b  = (const float*)d_in[11];
    const float* ff1_w  = (const float*)d_in[12];
    const float* ff1_b  = (const float*)d_in[13];
    const float* ff2_w  = (const float*)d_in[14];
    const float* ff2_b  = (const float*)d_in[15];
    const float* struct_bias = (const float*)d_in[16];
    const float* head_ln_g = (const float*)d_in[17];
    const float* head_ln_b = (const float*)d_in[18];
    const float* head_w = (const float*)d_in[19];
    const float* head_b = (const float*)d_in[20];
    const float* adjacency = (const float*)d_in[21];
    const unsigned char* is_atom_raw = (const unsigned char*)d_in[22];
    const int* atom_id  = (const int*)d_in[23];
    const unsigned char* mask_raw = (const unsigned char*)d_in[24];
    const int* root_idx = (const int*)d_in[25];
    float* outp = (float*)d_out;

    float *h, *x, *qkv, *o, *f;
    int *im, *mk;
    cudaGetSymbolAddress((void**)&h,  g_h);
    cudaGetSymbolAddress((void**)&x,  g_x);
    cudaGetSymbolAddress((void**)&qkv, g_qkv);
    cudaGetSymbolAddress((void**)&o,  g_o);
    cudaGetSymbolAddress((void**)&f,  g_f);
    cudaGetSymbolAddress((void**)&im, g_isatom);
    cudaGetSymbolAddress((void**)&mk, g_mask);

    const int ATTN_SMEM = (64*128*2 + 64*33)*4 + 64*4;
    cudaFuncSetAttribute(attn_kernel, cudaFuncAttributeMaxDynamicSharedMemorySize, ATTN_SMEM);

    norm_bool_kernel<<<1, 256>>>(is_atom_raw, ROWS, im);
    norm_bool_kernel<<<1, 256>>>(mask_raw,    ROWS, mk);
    embed_kernel<<<ROWS, 128>>>(atom_embed, cons_embed, atom_id, im, x);

    gemm_kernel<0><<<dim3(2,64), 256>>>(x, in_w, in_b, nullptr, h, ROWS, DD, DD);

    for (int l = 0; l < LL; l++) {
        ln_kernel<<<ROWS, 128>>>(h, ln1_g + l*DD, ln1_b + l*DD, x);
        gemm_kernel<0><<<dim3(6,64), 256>>>(x, qkv_w + (size_t)l*3*DD*DD, qkv_b + l*3*DD,
                                            nullptr, qkv, ROWS, 3*DD, DD);
        attn_kernel<<<dim3(NN/32, BB), 256, ATTN_SMEM>>>(qkv, adjacency, mk,
                                                         struct_bias + l, o);
        gemm_kernel<1><<<dim3(2,64), 256>>>(o, out_w + (size_t)l*DD*DD, out_b + l*DD,
                                            h, h, ROWS, DD, DD);
        ln_kernel<<<ROWS, 128>>>(h, ln2_g + l*DD, ln2_b + l*DD, x);
        gemm_kernel<2><<<dim3(8,64), 256>>>(x, ff1_w + (size_t)l*4*DD*DD, ff1_b + l*4*DD,
                                            nullptr, f, ROWS, 4*DD, DD);
        gemm_kernel<1><<<dim3(2,64), 256>>>(f, ff2_w + (size_t)l*DD*4*DD, ff2_b + l*DD,
                                            h, h, ROWS, DD, 4*DD);
    }

    head_kernel<<<1, 128>>>(h, head_ln_g, head_ln_b, head_w, head_b, root_idx, outp);
}

// round 2
// speedup vs baseline: 1.2840x; 1.2840x over previous
#include <cuda_runtime.h>
#include <cuda_bf16.h>
#include <math.h>

// ---------------- problem constants ----------------
#define BB 2
#define NN 2048
#define DD 128
#define HH 8
#define DH 16
#define LL 3
#define ROWS (BB*NN)        // 4096
#define SCALE 0.25f         // 1/sqrt(16)
#define NEG   (-1e9f)
#define EPS   1e-5f
#define KS    8             // key-split chunks
#define CHUNK (NN/KS)       // 256 keys per chunk

// ---------------- scratch (device globals; no allocation allowed) ----------
__device__ float g_h  [ROWS*DD];       // residual stream
__device__ float g_x  [ROWS*DD];       // LN output
__device__ float g_qkv[ROWS*3*DD];     // qkv
__device__ float g_o  [ROWS*DD];       // attention out
__device__ float g_f  [ROWS*4*DD];     // ff hidden
__device__ float g_pacc[ROWS*HH*KS*16]; // split-K partial accumulators
__device__ float g_pml [ROWS*HH*KS*2];  // split-K partial (m, l)
__device__ int   g_isatom[ROWS];
__device__ int   g_mask  [ROWS];

// ---------------- bool normalization (format-agnostic) ----------------
__global__ void norm_bool_kernel(const unsigned char* __restrict__ raw, int count,
                                 int* __restrict__ out) {
    __shared__ int s_other;
    if (threadIdx.x == 0) s_other = 0;
    __syncthreads();
    const unsigned int* w = (const unsigned int*)raw;
    int nw = count / 4;
    int other = 0;
    for (int i = threadIdx.x; i < nw; i += blockDim.x) {
        unsigned int v = w[i];
        if (v != 0u && v != 1u && v != 0x3f800000u) other = 1;
    }
    if (other) atomicOr(&s_other, 1);
    __syncthreads();
    bool byteFmt = (s_other != 0);
    for (int i = threadIdx.x; i < count; i += blockDim.x) {
        out[i] = byteFmt ? (raw[i] != 0) : (w[i] != 0u);
    }
}

// ---------------- embedding gather ----------------
__global__ void embed_kernel(const float* __restrict__ atom_embed,
                             const float* __restrict__ cons_embed,
                             const int* __restrict__ atom_id,
                             const int* __restrict__ isatom,
                             float* __restrict__ e) {
    int row = blockIdx.x, t = threadIdx.x;
    int id = atom_id[row];
    id = id < 0 ? 0 : (id > 31 ? 31 : id);
    float v = isatom[row] ? atom_embed[id*DD + t] : cons_embed[t];
    e[row*DD + t] = v;
}

// ---------------- block reduction helper (128 threads) ----------------
__device__ __forceinline__ float blockReduceSum128(float v, float* sred) {
    #pragma unroll
    for (int o = 16; o; o >>= 1) v += __shfl_xor_sync(0xffffffffu, v, o);
    int wid = threadIdx.x >> 5;
    if ((threadIdx.x & 31) == 0) sred[wid] = v;
    __syncthreads();
    float r = sred[0] + sred[1] + sred[2] + sred[3];
    __syncthreads();
    return r;
}

// ---------------- LayerNorm (one row of 128 per block) ----------------
__global__ void ln_kernel(const float* __restrict__ in, const float* __restrict__ g,
                          const float* __restrict__ b, float* __restrict__ out) {
    __shared__ float sred[4];
    int row = blockIdx.x, t = threadIdx.x;
    float v = in[row*DD + t];
    float mean = blockReduceSum128(v, sred) * (1.0f/DD);
    float d = v - mean;
    float var = blockReduceSum128(d*d, sred) * (1.0f/DD);
    out[row*DD + t] = d * rsqrtf(var + EPS) * g[t] + b[t];
}

// ---------------- GEMM: C[M,Nc] = A[M,K] @ W[Nc,K]^T + bias (+epilogue) -----
// MODE 0: +bias  | MODE 1: +bias +res (may alias C) | MODE 2: +bias then GELU
template<int MODE>
__global__ void gemm_kernel(const float* __restrict__ A, const float* __restrict__ W,
                            const float* __restrict__ bias, const float* __restrict__ res,
                            float* __restrict__ C, int M, int Nc, int K) {
    __shared__ float As[64*33];
    __shared__ float Ws[64*33];
    int tx = threadIdx.x & 15, ty = threadIdx.x >> 4;
    int m0 = blockIdx.y * 64, n0 = blockIdx.x * 64;
    float acc[4][4] = {};
    for (int k0 = 0; k0 < K; k0 += 32) {
        #pragma unroll
        for (int r = 0; r < 2; r++) {
            int idx = threadIdx.x + r*256;       // 0..511 float4 slots
            int row = idx >> 3, c4 = idx & 7;
            float4 va = *(const float4*)(A + (size_t)(m0+row)*K + k0 + c4*4);
            float* da = As + row*33 + c4*4;
            da[0]=va.x; da[1]=va.y; da[2]=va.z; da[3]=va.w;
            float4 vb = *(const float4*)(W + (size_t)(n0+row)*K + k0 + c4*4);
            float* db = Ws + row*33 + c4*4;
            db[0]=vb.x; db[1]=vb.y; db[2]=vb.z; db[3]=vb.w;
        }
        __syncthreads();
        #pragma unroll
        for (int kk = 0; kk < 32; kk++) {
            float a[4], w[4];
            #pragma unroll
            for (int i = 0; i < 4; i++) a[i] = As[(ty*4+i)*33 + kk];
            #pragma unroll
            for (int j = 0; j < 4; j++) w[j] = Ws[(tx*4+j)*33 + kk];
            #pragma unroll
            for (int i = 0; i < 4; i++)
                #pragma unroll
                for (int j = 0; j < 4; j++)
                    acc[i][j] += a[i] * w[j];
        }
        __syncthreads();
    }
    #pragma unroll
    for (int i = 0; i < 4; i++) {
        int r = m0 + ty*4 + i;
        #pragma unroll
        for (int j = 0; j < 4; j++) {
            int c = n0 + tx*4 + j;
            float v = acc[i][j] + bias[c];
            if (MODE == 1) v += res[(size_t)r*Nc + c];
            if (MODE == 2) v = 0.5f * v * (1.0f + erff(v * 0.70710678118654752f));
            C[(size_t)r*Nc + c] = v;
        }
    }
}

// ---------------- split-K flash attention (partials) ----------------
// Grid: (N/64, KS*B), 512 threads. Thread (h=tid>>6, qi=tid&63) owns one
// (head, query-row); processes CHUNK keys, writes unnormalized partials.
__global__ __launch_bounds__(512)
void attn_part_kernel(const float* __restrict__ qkv, const float* __restrict__ adj,
                      const int* __restrict__ mask, const float* __restrict__ sbp,
                      float* __restrict__ pacc, float* __restrict__ pml) {
    extern __shared__ float sm[];
    float* sK    = sm;                    // 64*128
    float* sV    = sK + 64*128;           // 64*128
    float* sBias = sV + 64*128;           // 64*65  (kj-major, padded)

    int b = blockIdx.y >> 3, ck = blockIdx.y & 7;
    int n0 = blockIdx.x * 64;
    int tid = threadIdx.x;
    int qi = tid & 63, hh = tid >> 6;
    float sb = *sbp;

    int qrow = b*NN + n0 + qi;
    float4 q4[4];
    const float4* qp = (const float4*)(qkv + (size_t)qrow*384 + hh*DH);
    #pragma unroll
    for (int i = 0; i < 4; i++) q4[i] = qp[i];

    float m = -INFINITY, l = 0.0f;
    float acc[16];
    #pragma unroll
    for (int d = 0; d < 16; d++) acc[d] = 0.0f;

    const float* adjb = adj + (size_t)b*NN*NN;
    const int* maskb = mask + b*NN;

    for (int k0 = ck*CHUNK; k0 < (ck+1)*CHUNK; k0 += 64) {
        // load K/V tiles (float4 slots: 2048 each, 512 threads x 4)
        #pragma unroll
        for (int r = 0; r < 4; r++) {
            int idx = tid + r*512;
            int row = idx >> 5, c4 = idx & 31;
            const float* base = qkv + (size_t)(b*NN + k0 + row)*384;
            *(float4*)(sK + row*128 + c4*4) = *(const float4*)(base + 128 + c4*4);
            *(float4*)(sV + row*128 + c4*4) = *(const float4*)(base + 256 + c4*4);
        }
        // load bias tile: sb*adj + additive mask, kj-major
        #pragma unroll
        for (int r = 0; r < 8; r++) {
            int idx = tid + r*512;               // 0..4095
            int q2 = idx >> 6, kj = idx & 63;
            int mq = maskb[n0 + q2], mk2 = maskb[k0 + kj];
            bool ok = (mq && mk2) || (!mq && (n0 + q2 == k0 + kj));
            float v = sb * adjb[(size_t)(n0 + q2)*NN + k0 + kj];
            sBias[kj*65 + q2] = ok ? v : v + NEG;
        }
        __syncthreads();

        #pragma unroll 4
        for (int kj = 0; kj < 64; kj++) {
            const float4* kp = (const float4*)(sK + kj*128 + hh*DH);
            float s = 0.0f;
            #pragma unroll
            for (int i = 0; i < 4; i++) {
                float4 kv = kp[i];
                s += q4[i].x*kv.x + q4[i].y*kv.y + q4[i].z*kv.z + q4[i].w*kv.w;
            }
            s = s*SCALE + sBias[kj*65 + qi];

            if (s > m) {
                float corr = __expf(m - s);
                m = s; l *= corr;
                #pragma unroll
                for (int d = 0; d < 16; d++) acc[d] *= corr;
            }
            float p = __expf(s - m);
            l += p;
            const float4* vp = (const float4*)(sV + kj*128 + hh*DH);
            #pragma unroll
            for (int i = 0; i < 4; i++) {
                float4 vv = vp[i];
                acc[i*4+0] += p*vv.x; acc[i*4+1] += p*vv.y;
                acc[i*4+2] += p*vv.z; acc[i*4+3] += p*vv.w;
            }
        }
        __syncthreads();
    }
    size_t p = ((size_t)qrow*HH + hh)*KS + ck;
    pml[p*2]   = m;
    pml[p*2+1] = l;
    #pragma unroll
    for (int d = 0; d < 16; d++) pacc[p*16 + d] = acc[d];
}

// ---------------- split-K reduce: combine KS partials ----------------
// One thread per (qrow, head).
__global__ void attn_reduce_kernel(const float* __restrict__ pacc,
                                   const float* __restrict__ pml,
                                   float* __restrict__ o) {
    int t = blockIdx.x * blockDim.x + threadIdx.x;     // 0..ROWS*HH-1
    if (t >= ROWS*HH) return;
    size_t base = (size_t)t * KS;
    float mv[KS], lv[KS];
    float M = -INFINITY;
    #pragma unroll
    for (int c = 0; c < KS; c++) {
        mv[c] = pml[(base+c)*2];
        lv[c] = pml[(base+c)*2+1];
        M = fmaxf(M, mv[c]);
    }
    float w[KS]; float L = 0.0f;
    #pragma unroll
    for (int c = 0; c < KS; c++) { w[c] = __expf(mv[c] - M); L += w[c]*lv[c]; }
    float inv = 1.0f / L;
    int qrow = t >> 3, hh = t & 7;
    float* op = o + (size_t)qrow*DD + hh*DH;
    #pragma unroll
    for (int d = 0; d < 16; d++) {
        float s = 0.0f;
        #pragma unroll
        for (int c = 0; c < KS; c++) s += w[c] * pacc[(base+c)*16 + d];
        op[d] = s * inv;
    }
}

// ---------------- head: gather root, LN, dot ----------------
__global__ void head_kernel(const float* __restrict__ h, const float* __restrict__ g,
                            const float* __restrict__ bb, const float* __restrict__ w,
                            const float* __restrict__ hb, const int* __restrict__ root,
                            float* __restrict__ out) {
    __shared__ float sred[4];
    int t = threadIdx.x;
    for (int b = 0; b < BB; b++) {
        int row = root[b];
        float v = h[((size_t)b*NN + row)*DD + t];
        float mean = blockReduceSum128(v, sred) * (1.0f/DD);
        float d = v - mean;
        float var = blockReduceSum128(d*d, sred) * (1.0f/DD);
        float p = d * rsqrtf(var + EPS) * g[t] + bb[t];
        float s = blockReduceSum128(p * w[t], sred);
        if (t == 0) out[b] = s + hb[0];
    }
}

// ---------------- launch ----------------
extern "C" void kernel_launch(void* const* d_in, const int* in_sizes, int n_in,
                              void* d_out, int out_size) {
    const float* atom_embed = (const float*)d_in[0];
    const float* cons_embed = (const float*)d_in[1];
    const float* in_w   = (const float*)d_in[2];
    const float* in_b   = (const float*)d_in[3];
    const float* qkv_w  = (const float*)d_in[4];
    const float* qkv_b  = (const float*)d_in[5];
    const float* out_w  = (const float*)d_in[6];
    const float* out_b  = (const float*)d_in[7];
    const float* ln1_g  = (const float*)d_in[8];
    const float* ln1_b  = (const float*)d_in[9];
    const float* ln2_g  = (const float*)d_in[10];
    const float* ln2_b  = (const float*)d_in[11];
    const float* ff1_w  = (const float*)d_in[12];
    const float* ff1_b  = (const float*)d_in[13];
    const float* ff2_w  = (const float*)d_in[14];
    const float* ff2_b  = (const float*)d_in[15];
    const float* struct_bias = (const float*)d_in[16];
    const float* head_ln_g = (const float*)d_in[17];
    const float* head_ln_b = (const float*)d_in[18];
    const float* head_w = (const float*)d_in[19];
    const float* head_b = (const float*)d_in[20];
    const float* adjacency = (const float*)d_in[21];
    const unsigned char* is_atom_raw = (const unsigned char*)d_in[22];
    const int* atom_id  = (const int*)d_in[23];
    const unsigned char* mask_raw = (const unsigned char*)d_in[24];
    const int* root_idx = (const int*)d_in[25];
    float* outp = (float*)d_out;

    float *h, *x, *qkv, *o, *f, *pacc, *pml;
    int *im, *mk;
    cudaGetSymbolAddress((void**)&h,  g_h);
    cudaGetSymbolAddress((void**)&x,  g_x);
    cudaGetSymbolAddress((void**)&qkv, g_qkv);
    cudaGetSymbolAddress((void**)&o,  g_o);
    cudaGetSymbolAddress((void**)&f,  g_f);
    cudaGetSymbolAddress((void**)&pacc, g_pacc);
    cudaGetSymbolAddress((void**)&pml,  g_pml);
    cudaGetSymbolAddress((void**)&im, g_isatom);
    cudaGetSymbolAddress((void**)&mk, g_mask);

    const int ATTN_SMEM = (64*128*2 + 64*65)*4;
    cudaFuncSetAttribute(attn_part_kernel, cudaFuncAttributeMaxDynamicSharedMemorySize, ATTN_SMEM);

    norm_bool_kernel<<<1, 256>>>(is_atom_raw, ROWS, im);
    norm_bool_kernel<<<1, 256>>>(mask_raw,    ROWS, mk);
    embed_kernel<<<ROWS, 128>>>(atom_embed, cons_embed, atom_id, im, x);

    gemm_kernel<0><<<dim3(2,64), 256>>>(x, in_w, in_b, nullptr, h, ROWS, DD, DD);

    for (int l = 0; l < LL; l++) {
        ln_kernel<<<ROWS, 128>>>(h, ln1_g + l*DD, ln1_b + l*DD, x);
        gemm_kernel<0><<<dim3(6,64), 256>>>(x, qkv_w + (size_t)l*3*DD*DD, qkv_b + l*3*DD,
                                            nullptr, qkv, ROWS, 3*DD, DD);
        attn_part_kernel<<<dim3(NN/64, KS*BB), 512, ATTN_SMEM>>>(qkv, adjacency, mk,
                                                                 struct_bias + l, pacc, pml);
        attn_reduce_kernel<<<ROWS*HH/256, 256>>>(pacc, pml, o);
        gemm_kernel<1><<<dim3(2,64), 256>>>(o, out_w + (size_t)l*DD*DD, out_b + l*DD,
                                            h, h, ROWS, DD, DD);
        ln_kernel<<<ROWS, 128>>>(h, ln2_g + l*DD, ln2_b + l*DD, x);
        gemm_kernel<2><<<dim3(8,64), 256>>>(x, ff1_w + (size_t)l*4*DD*DD, ff1_b + l*4*DD,
                                            nullptr, f, ROWS, 4*DD, DD);
        gemm_kernel<1><<<dim3(2,64), 256>>>(f, ff2_w + (size_t)l*DD*4*DD, ff2_b + l*DD,
                                            h, h, ROWS, DD, 4*DD);
    }

    head_kernel<<<1, 128>>>(h, head_ln_g, head_ln_b, head_w, head_b, root_idx, outp);
}

// round 4
// speedup vs baseline: 1.3464x; 1.0486x over previous
#include <cuda_runtime.h>
#include <cuda_bf16.h>
#include <math.h>

// ---------------- problem constants ----------------
#define BB 2
#define NN 2048
#define DD 128
#define HH 8
#define DH 16
#define LL 3
#define ROWS (BB*NN)        // 4096
#define SCALE 0.25f         // 1/sqrt(16)
#define LOG2E 1.4426950408889634f
#define NEGL  (-1.5e9f)     // masked logit, log2 domain
#define EPS   1e-5f
#define KS    8             // key-split chunks
#define CHUNK (NN/KS)       // 256 keys per chunk

__device__ __forceinline__ float ex2(float x) {
    float r; asm("ex2.approx.ftz.f32 %0,%1;" : "=f"(r) : "f"(x)); return r;
}

// ---------------- scratch (device globals; no allocation allowed) ----------
__device__ float g_h  [ROWS*DD];
__device__ float g_x  [ROWS*DD];
__device__ float g_qkv[ROWS*3*DD];
__device__ float g_o  [ROWS*DD];
__device__ float g_f  [ROWS*4*DD];
__device__ float g_pacc[ROWS*HH*KS*16];
__device__ float g_pml [ROWS*HH*KS*2];
__device__ float g_mean[ROWS];
__device__ float g_rstd[ROWS];
__device__ int   g_isatom[ROWS];
__device__ int   g_mask  [ROWS];

// ---------------- bool normalization (format-agnostic) ----------------
__global__ void norm_bool_kernel(const unsigned char* __restrict__ raw, int count,
                                 int* __restrict__ out) {
    __shared__ int s_other;
    if (threadIdx.x == 0) s_other = 0;
    __syncthreads();
    const unsigned int* w = (const unsigned int*)raw;
    int nw = count / 4;
    int other = 0;
    for (int i = threadIdx.x; i < nw; i += blockDim.x) {
        unsigned int v = w[i];
        if (v != 0u && v != 1u && v != 0x3f800000u) other = 1;
    }
    if (other) atomicOr(&s_other, 1);
    __syncthreads();
    bool byteFmt = (s_other != 0);
    for (int i = threadIdx.x; i < count; i += blockDim.x) {
        out[i] = byteFmt ? (raw[i] != 0) : (w[i] != 0u);
    }
}

// ---------------- embedding gather ----------------
__global__ void embed_kernel(const float* __restrict__ atom_embed,
                             const float* __restrict__ cons_embed,
                             const int* __restrict__ atom_id,
                             const int* __restrict__ isatom,
                             float* __restrict__ e) {
    int row = blockIdx.x, t = threadIdx.x;
    int id = atom_id[row];
    id = id < 0 ? 0 : (id > 31 ? 31 : id);
    float v = isatom[row] ? atom_embed[id*DD + t] : cons_embed[t];
    e[row*DD + t] = v;
}

// ---------------- block reduction helper (128 threads) ----------------
__device__ __forceinline__ float blockReduceSum128(float v, float* sred) {
    #pragma unroll
    for (int o = 16; o; o >>= 1) v += __shfl_xor_sync(0xffffffffu, v, o);
    int wid = threadIdx.x >> 5;
    if ((threadIdx.x & 31) == 0) sred[wid] = v;
    __syncthreads();
    float r = sred[0] + sred[1] + sred[2] + sred[3];
    __syncthreads();
    return r;
}

// ---------------- LN stats: per-row mean / rstd ----------------
__global__ void stats_kernel(const float* __restrict__ in,
                             float* __restrict__ mean, float* __restrict__ rstd) {
    __shared__ float sred[4];
    int row = blockIdx.x, t = threadIdx.x;
    float v = in[row*DD + t];
    float mu = blockReduceSum128(v, sred) * (1.0f/DD);
    float d = v - mu;
    float var = blockReduceSum128(d*d, sred) * (1.0f/DD);
    if (t == 0) { mean[row] = mu; rstd[row] = rsqrtf(var + EPS); }
}

// ---------------- GEMM: C[M,Nc] = A'[M,K] @ W[Nc,K]^T + bias (+epilogue) ----
// A' = LNA ? LayerNorm(A) via (mean,rstd,g,b) applied during staging : A.
// MODE 0: +bias | MODE 1: +bias +res (res may alias C) | MODE 2: +bias, GELU
template<int MODE, int TM, bool LNA>
__global__ __launch_bounds__(256)
void gemm_kernel(const float* __restrict__ A, const float* __restrict__ W,
                 const float* __restrict__ bias, const float* __restrict__ res,
                 float* __restrict__ C, int M, int Nc, int K,
                 const float* __restrict__ meanp, const float* __restrict__ rstdp,
                 const float* __restrict__ lng, const float* __restrict__ lnb) {
    __shared__ float As[TM*33];
    __shared__ float Ws[64*33];
    const int t = threadIdx.x;
    const int tx = t & 15, ty = t >> 4;
    const int m0 = blockIdx.y * TM, n0 = blockIdx.x * 64;
    constexpr int RM = TM / 16;            // rows per thread (2 or 4)
    float acc[RM][4] = {};

    for (int k0 = 0; k0 < K; k0 += 32) {
        // stage A (TM x 32), optionally applying LayerNorm
        #pragma unroll
        for (int r = 0; r < TM/32; r++) {
            int idx = t + r*256;                 // TM*8 float4 slots
            int row = idx >> 3, c4 = idx & 7;
            float4 va = *(const float4*)(A + (size_t)(m0+row)*K + k0 + c4*4);
            if (LNA) {
                float mu = meanp[m0+row], rs = rstdp[m0+row];
                float4 g4 = *(const float4*)(lng + k0 + c4*4);
                float4 b4 = *(const float4*)(lnb + k0 + c4*4);
                va.x = (va.x - mu)*rs*g4.x + b4.x;
                va.y = (va.y - mu)*rs*g4.y + b4.y;
                va.z = (va.z - mu)*rs*g4.z + b4.z;
                va.w = (va.w - mu)*rs*g4.w + b4.w;
            }
            float* da = As + row*33 + c4*4;
            da[0]=va.x; da[1]=va.y; da[2]=va.z; da[3]=va.w;
        }
        // stage W (64 x 32)
        #pragma unroll
        for (int r = 0; r < 2; r++) {
            int idx = t + r*256;
            int row = idx >> 3, c4 = idx & 7;
            float4 vb = *(const float4*)(W + (size_t)(n0+row)*K + k0 + c4*4);
            float* db = Ws + row*33 + c4*4;
            db[0]=vb.x; db[1]=vb.y; db[2]=vb.z; db[3]=vb.w;
        }
        __syncthreads();
        #pragma unroll
        for (int kk = 0; kk < 32; kk++) {
            float a[RM], w[4];
            #pragma unroll
            for (int i = 0; i < RM; i++) a[i] = As[(ty*RM+i)*33 + kk];
            #pragma unroll
            for (int j = 0; j < 4; j++) w[j] = Ws[(tx*4+j)*33 + kk];
            #pragma unroll
            for (int i = 0; i < RM; i++)
                #pragma unroll
                for (int j = 0; j < 4; j++)
                    acc[i][j] += a[i] * w[j];
        }
        __syncthreads();
    }
    #pragma unroll
    for (int i = 0; i < RM; i++) {
        int r = m0 + ty*RM + i;
        #pragma unroll
        for (int j = 0; j < 4; j++) {
            int c = n0 + tx*4 + j;
            float v = acc[i][j] + bias[c];
            if (MODE == 1) v += res[(size_t)r*Nc + c];
            if (MODE == 2) v = 0.5f * v * (1.0f + erff(v * 0.70710678118654752f));
            C[(size_t)r*Nc + c] = v;
        }
    }
}

// ---------------- split-K flash attention (partials, 2-key pairing) --------
// Grid: (N/64, KS*B), 512 threads. Thread (h=tid>>6, qi=tid&63) owns one
// (head, query-row); processes CHUNK keys, writes unnormalized partials.
__global__ __launch_bounds__(512)
void attn_part_kernel(const float* __restrict__ qkv, const float* __restrict__ adj,
                      const int* __restrict__ mask, const float* __restrict__ sbp,
                      float* __restrict__ pacc, float* __restrict__ pml) {
    extern __shared__ float sm[];
    float* sK    = sm;                    // 64*128
    float* sV    = sK + 64*128;           // 64*128
    float* sBias = sV + 64*128;           // 64*65  (kj-major, padded)

    const int b = blockIdx.y >> 3, ck = blockIdx.y & 7;
    const int n0 = blockIdx.x * 64;
    const int tid = threadIdx.x;
    const int qi = tid & 63, hh = tid >> 6;
    const float sbl = (*sbp) * LOG2E;
    const float SC2 = SCALE * LOG2E;

    const int qrow = b*NN + n0 + qi;
    float4 q4[4];
    {
        const float4* qp = (const float4*)(qkv + (size_t)qrow*384 + hh*DH);
        #pragma unroll
        for (int i = 0; i < 4; i++) q4[i] = qp[i];
    }

    float m = -INFINITY, l = 0.0f;
    float acc[16];
    #pragma unroll
    for (int d = 0; d < 16; d++) acc[d] = 0.0f;

    const float* adjb = adj + (size_t)b*NN*NN;
    const int* maskb = mask + b*NN;

    for (int k0 = ck*CHUNK; k0 < (ck+1)*CHUNK; k0 += 64) {
        // K/V tiles
        #pragma unroll
        for (int r = 0; r < 4; r++) {
            int idx = tid + r*512;
            int row = idx >> 5, c4 = idx & 31;
            const float* base = qkv + (size_t)(b*NN + k0 + row)*384;
            *(float4*)(sK + row*128 + c4*4) = *(const float4*)(base + 128 + c4*4);
            *(float4*)(sV + row*128 + c4*4) = *(const float4*)(base + 256 + c4*4);
        }
        // bias tile: log2-domain (sb*adj)*log2e + mask, kj-major
        #pragma unroll
        for (int r = 0; r < 8; r++) {
            int idx = tid + r*512;
            int q2i = idx >> 6, kj = idx & 63;
            int mq = maskb[n0 + q2i], mk2 = maskb[k0 + kj];
            bool ok = (mq && mk2) || (!mq && (n0 + q2i == k0 + kj));
            float v = sbl * adjb[(size_t)(n0 + q2i)*NN + k0 + kj];
            sBias[kj*65 + q2i] = ok ? v : v + NEGL;
        }
        __syncthreads();

        for (int kj = 0; kj < 64; kj += 2) {
            const float4* kp0 = (const float4*)(sK + kj*128 + hh*DH);
            const float4* kp1 = (const float4*)(sK + (kj+1)*128 + hh*DH);
            float s0 = 0.0f, s1 = 0.0f;
            #pragma unroll
            for (int i = 0; i < 4; i++) {
                float4 k0v = kp0[i], k1v = kp1[i];
                s0 += q4[i].x*k0v.x + q4[i].y*k0v.y + q4[i].z*k0v.z + q4[i].w*k0v.w;
                s1 += q4[i].x*k1v.x + q4[i].y*k1v.y + q4[i].z*k1v.z + q4[i].w*k1v.w;
            }
            s0 = fmaf(s0, SC2, sBias[kj*65 + qi]);
            s1 = fmaf(s1, SC2, sBias[(kj+1)*65 + qi]);

            float mn = fmaxf(m, fmaxf(s0, s1));
            if (mn > m) {
                float corr = ex2(m - mn);
                l *= corr;
                #pragma unroll
                for (int d = 0; d < 16; d++) acc[d] *= corr;
                m = mn;
            }
            float p0 = ex2(s0 - m);
            float p1 = ex2(s1 - m);
            l += p0 + p1;
            const float4* vp0 = (const float4*)(sV + kj*128 + hh*DH);
            const float4* vp1 = (const float4*)(sV + (kj+1)*128 + hh*DH);
            #pragma unroll
            for (int i = 0; i < 4; i++) {
                float4 v0 = vp0[i], v1 = vp1[i];
                acc[i*4+0] += p0*v0.x + p1*v1.x;
                acc[i*4+1] += p0*v0.y + p1*v1.y;
                acc[i*4+2] += p0*v0.z + p1*v1.z;
                acc[i*4+3] += p0*v0.w + p1*v1.w;
            }
        }
        __syncthreads();
    }
    size_t p = ((size_t)qrow*HH + hh)*KS + ck;
    pml[p*2]   = m;
    pml[p*2+1] = l;
    #pragma unroll
    for (int d = 0; d < 16; d++) pacc[p*16 + d] = acc[d];
}

// ---------------- split-K reduce (base-2 weights) ----------------
__global__ void attn_reduce_kernel(const float* __restrict__ pacc,
                                   const float* __restrict__ pml,
                                   float* __restrict__ o) {
    int t = blockIdx.x * blockDim.x + threadIdx.x;     // 0..ROWS*HH-1
    if (t >= ROWS*HH) return;
    size_t base = (size_t)t * KS;
    float mv[KS], lv[KS];
    float M = -INFINITY;
    #pragma unroll
    for (int c = 0; c < KS; c++) {
        mv[c] = pml[(base+c)*2];
        lv[c] = pml[(base+c)*2+1];
        M = fmaxf(M, mv[c]);
    }
    float w[KS]; float L = 0.0f;
    #pragma unroll
    for (int c = 0; c < KS; c++) { w[c] = ex2(mv[c] - M); L += w[c]*lv[c]; }
    float inv = 1.0f / L;
    int qrow = t >> 3, hh = t & 7;
    float* op = o + (size_t)qrow*DD + hh*DH;
    #pragma unroll
    for (int d = 0; d < 16; d++) {
        float s = 0.0f;
        #pragma unroll
        for (int c = 0; c < KS; c++) s += w[c] * pacc[(base+c)*16 + d];
        op[d] = s * inv;
    }
}

// ---------------- head: gather root, LN, dot ----------------
__global__ void head_kernel(const float* __restrict__ h, const float* __restrict__ g,
                            const float* __restrict__ bb, const float* __restrict__ w,
                            const float* __restrict__ hb, const int* __restrict__ root,
                            float* __restrict__ out) {
    __shared__ float sred[4];
    int t = threadIdx.x;
    for (int b = 0; b < BB; b++) {
        int row = root[b];
        float v = h[((size_t)b*NN + row)*DD + t];
        float mean = blockReduceSum128(v, sred) * (1.0f/DD);
        float d = v - mean;
        float var = blockReduceSum128(d*d, sred) * (1.0f/DD);
        float p = d * rsqrtf(var + EPS) * g[t] + bb[t];
        float s = blockReduceSum128(p * w[t], sred);
        if (t == 0) out[b] = s + hb[0];
    }
}

// ---------------- launch ----------------
extern "C" void kernel_launch(void* const* d_in, const int* in_sizes, int n_in,
                              void* d_out, int out_size) {
    const float* atom_embed = (const float*)d_in[0];
    const float* cons_embed = (const float*)d_in[1];
    const float* in_w   = (const float*)d_in[2];
    const float* in_b   = (const float*)d_in[3];
    const float* qkv_w  = (const float*)d_in[4];
    const float* qkv_b  = (const float*)d_in[5];
    const float* out_w  = (const float*)d_in[6];
    const float* out_b  = (const float*)d_in[7];
    const float* ln1_g  = (const float*)d_in[8];
    const float* ln1_b  = (const float*)d_in[9];
    const float* ln2_g  = (const float*)d_in[10];
    const float* ln2_b  = (const float*)d_in[11];
    const float* ff1_w  = (const float*)d_in[12];
    const float* ff1_b  = (const float*)d_in[13];
    const float* ff2_w  = (const float*)d_in[14];
    const float* ff2_b  = (const float*)d_in[15];
    const float* struct_bias = (const float*)d_in[16];
    const float* head_ln_g = (const float*)d_in[17];
    const float* head_ln_b = (const float*)d_in[18];
    const float* head_w = (const float*)d_in[19];
    const float* head_b = (const float*)d_in[20];
    const float* adjacency = (const float*)d_in[21];
    const unsigned char* is_atom_raw = (const unsigned char*)d_in[22];
    const int* atom_id  = (const int*)d_in[23];
    const unsigned char* mask_raw = (const unsigned char*)d_in[24];
    const int* root_idx = (const int*)d_in[25];
    float* outp = (float*)d_out;

    float *h, *x, *qkv, *o, *f, *pacc, *pml, *mean, *rstd;
    int *im, *mk;
    cudaGetSymbolAddress((void**)&h,  g_h);
    cudaGetSymbolAddress((void**)&x,  g_x);
    cudaGetSymbolAddress((void**)&qkv, g_qkv);
    cudaGetSymbolAddress((void**)&o,  g_o);
    cudaGetSymbolAddress((void**)&f,  g_f);
    cudaGetSymbolAddress((void**)&pacc, g_pacc);
    cudaGetSymbolAddress((void**)&pml,  g_pml);
    cudaGetSymbolAddress((void**)&mean, g_mean);
    cudaGetSymbolAddress((void**)&rstd, g_rstd);
    cudaGetSymbolAddress((void**)&im, g_isatom);
    cudaGetSymbolAddress((void**)&mk, g_mask);

    const int ATTN_SMEM = (64*128*2 + 64*65)*4;
    cudaFuncSetAttribute(attn_part_kernel, cudaFuncAttributeMaxDynamicSharedMemorySize, ATTN_SMEM);

    norm_bool_kernel<<<1, 256>>>(is_atom_raw, ROWS, im);
    norm_bool_kernel<<<1, 256>>>(mask_raw,    ROWS, mk);
    embed_kernel<<<ROWS, 128>>>(atom_embed, cons_embed, atom_id, im, x);

    gemm_kernel<0,32,false><<<dim3(2,128), 256>>>(x, in_w, in_b, nullptr, h,
                                                  ROWS, DD, DD, nullptr, nullptr, nullptr, nullptr);

    for (int l = 0; l < LL; l++) {
        stats_kernel<<<ROWS, 128>>>(h, mean, rstd);
        gemm_kernel<0,64,true><<<dim3(6,64), 256>>>(h, qkv_w + (size_t)l*3*DD*DD,
                                                    qkv_b + l*3*DD, nullptr, qkv,
                                                    ROWS, 3*DD, DD,
                                                    mean, rstd, ln1_g + l*DD, ln1_b + l*DD);
        attn_part_kernel<<<dim3(NN/64, KS*BB), 512, ATTN_SMEM>>>(qkv, adjacency, mk,
                                                                 struct_bias + l, pacc, pml);
        attn_reduce_kernel<<<ROWS*HH/256, 256>>>(pacc, pml, o);
        gemm_kernel<1,32,false><<<dim3(2,128), 256>>>(o, out_w + (size_t)l*DD*DD,
                                                      out_b + l*DD, h, h,
                                                      ROWS, DD, DD, nullptr, nullptr, nullptr, nullptr);
        stats_kernel<<<ROWS, 128>>>(h, mean, rstd);
        gemm_kernel<2,64,true><<<dim3(8,64), 256>>>(h, ff1_w + (size_t)l*4*DD*DD,
                                                    ff1_b + l*4*DD, nullptr, f,
                                                    ROWS, 4*DD, DD,
                                                    mean, rstd, ln2_g + l*DD, ln2_b + l*DD);
        gemm_kernel<1,32,false><<<dim3(2,128), 256>>>(f, ff2_w + (size_t)l*DD*4*DD,
                                                      ff2_b + l*DD, h, h,
                                                      ROWS, DD, 4*DD, nullptr, nullptr, nullptr, nullptr);
    }

    head_kernel<<<1, 128>>>(h, head_ln_g, head_ln_b, head_w, head_b, root_idx, outp);
}